// round 15
// baseline (speedup 1.0000x reference)
#include <cuda_runtime.h>
#include <cuda_fp16.h>
#include <cstdint>
#include <math.h>

// ---------------------------------------------------------------------------
// Shapes fixed by the dataset
#define D_DIM   256
#define E_DIM   256
#define K_NEIGH 32
#define N_NODES 200000
#define B_PAD   50048          // 782 * 64  (GEMM M-tile padded)

// Scratch (__device__ globals: no allocations allowed)
__device__ __half g_X [(size_t)B_PAD * 512];    // activation (fp16, single plane)
__device__ __half g_Wt[256 * 512];              // W^T single plane (fp16) [e][k]
__device__ float  g_bc[256];                    // fused bias
__device__ __half g_F16[(size_t)N_NODES * 256]; // fp16 feature table (neigh path)

// ---------------------------------------------------------------------------
// Setup kernel: merged fp32->fp16 feature convert + fused-weight prep.
// Convert: 2 float4 per thread at COALESCED grid stride (MLP=2).
// blocks [0,25000): convert; [25000,25513): prep.
// ---------------------------------------------------------------------------
#define CONV_BLOCKS 25000
#define CONV_STRIDE ((size_t)CONV_BLOCKS * 256)     // 6.4M float4s per pass

__global__ void __launch_bounds__(256) setup_kernel(const float* __restrict__ features,
                                                    const float* __restrict__ W_init,
                                                    const float* __restrict__ b_init,
                                                    const float* __restrict__ W_final,
                                                    const float* __restrict__ b_final) {
    if (blockIdx.x < CONV_BLOCKS) {
        const size_t i0 = (size_t)blockIdx.x * 256 + threadIdx.x;
        const size_t i1 = i0 + CONV_STRIDE;
        float4 v0 = ((const float4*)features)[i0];
        float4 v1 = ((const float4*)features)[i1];
        {
            __half2 p0 = __floats2half2_rn(v0.x, v0.y);
            __half2 p1 = __floats2half2_rn(v0.z, v0.w);
            uint2 u; u.x = *(uint32_t*)&p0; u.y = *(uint32_t*)&p1;
            *(uint2*)(g_F16 + i0 * 4) = u;
        }
        {
            __half2 p0 = __floats2half2_rn(v1.x, v1.y);
            __half2 p1 = __floats2half2_rn(v1.z, v1.w);
            uint2 u; u.x = *(uint32_t*)&p0; u.y = *(uint32_t*)&p1;
            *(uint2*)(g_F16 + i1 * 4) = u;
        }
        return;
    }

    __shared__ float sh[256];
    const int d = blockIdx.x - CONV_BLOCKS;
    const int e = threadIdx.x;

    if (d < 256) {
        sh[e] = W_init[d * 256 + e];
        __syncthreads();
        float s0 = 0.f, s1 = 0.f, s2 = 0.f, s3 = 0.f;
#pragma unroll 8
        for (int j = 0; j < 256; j += 4) {
            s0 += sh[j + 0] * W_final[(j + 0) * 256 + e];
            s1 += sh[j + 1] * W_final[(j + 1) * 256 + e];
            s2 += sh[j + 2] * W_final[(j + 2) * 256 + e];
            s3 += sh[j + 3] * W_final[(j + 3) * 256 + e];
        }
        g_Wt[e * 512 + d] = __float2half_rn((s0 + s1) + (s2 + s3));
    } else if (d < 512) {
        g_Wt[e * 512 + d] = __float2half_rn(W_final[d * 256 + e]);
    } else {
        sh[e] = b_init[e];
        __syncthreads();
        float s0 = 0.f, s1 = 0.f, s2 = 0.f, s3 = 0.f;
#pragma unroll 8
        for (int j = 0; j < 256; j += 4) {
            s0 += sh[j + 0] * W_final[(j + 0) * 256 + e];
            s1 += sh[j + 1] * W_final[(j + 1) * 256 + e];
            s2 += sh[j + 2] * W_final[(j + 2) * 256 + e];
            s3 += sh[j + 3] * W_final[(j + 3) * 256 + e];
        }
        g_bc[e] = b_final[e] + (s0 + s1) + (s2 + s3);
    }
}

// ---------------------------------------------------------------------------
// Kernel 1 (proven body; chunk offset added): gather + weighted-mean -> X fp16.
// ---------------------------------------------------------------------------
static __device__ __forceinline__ void store4_h(float4 v, __half* p) {
    __half2 H0 = __floats2half2_rn(v.x, v.y);
    __half2 H1 = __floats2half2_rn(v.z, v.w);
    uint2 u;
    u.x = *(uint32_t*)&H0; u.y = *(uint32_t*)&H1;
    *(uint2*)p = u;
}

__global__ void __launch_bounds__(256) gather_kernel(const int*   __restrict__ nodes,
                                                     const int*   __restrict__ neigh_idx,
                                                     const float* __restrict__ neigh_w,
                                                     const float* __restrict__ features,
                                                     int b_off, int B) {
    const int wid  = threadIdx.x >> 5;
    const int lane = threadIdx.x & 31;
    const int b    = b_off + blockIdx.x * 8 + wid;
    if (b >= B_PAD) return;

    __half* x = g_X + (size_t)b * 512;

    float4 s0, s1, a0, a1;
    if (b < B) {
        const int node = nodes[b];
        const float4* fs = (const float4*)(features + (size_t)node * D_DIM);
        s0 = fs[lane];
        s1 = fs[lane + 32];

        const float w_mine   = neigh_w[b * K_NEIGH + lane];
        const int   idx_mine = neigh_idx[b * K_NEIGH + lane];
        float ws = w_mine;
#pragma unroll
        for (int o = 16; o > 0; o >>= 1)
            ws += __shfl_xor_sync(0xffffffffu, ws, o);
        const float inv = 1.0f / ws;

        a0 = make_float4(0.f, 0.f, 0.f, 0.f);
        a1 = make_float4(0.f, 0.f, 0.f, 0.f);
#pragma unroll 8
        for (int k = 0; k < K_NEIGH; k++) {
            const float wk = __shfl_sync(0xffffffffu, w_mine, k) * inv;
            const int   ik = __shfl_sync(0xffffffffu, idx_mine, k);
            uint4 v = *(const uint4*)(g_F16 + (size_t)ik * 256 + lane * 8);
            float2 f0 = __half22float2(*(__half2*)&v.x);
            float2 f1 = __half22float2(*(__half2*)&v.y);
            float2 f2 = __half22float2(*(__half2*)&v.z);
            float2 f3 = __half22float2(*(__half2*)&v.w);
            a0.x += wk * f0.x; a0.y += wk * f0.y; a0.z += wk * f1.x; a0.w += wk * f1.y;
            a1.x += wk * f2.x; a1.y += wk * f2.y; a1.z += wk * f3.x; a1.w += wk * f3.y;
        }
    } else {
        s0 = s1 = a0 = a1 = make_float4(0.f, 0.f, 0.f, 0.f);
    }

    store4_h(s0, x + lane * 4);
    store4_h(s1, x + 128 + lane * 4);
    store4_h(a0, x + 256 + lane * 8);
    store4_h(a1, x + 256 + lane * 8 + 4);
}

// ---------------------------------------------------------------------------
// Kernel 2 (proven body; tile offset added): tensor-core GEMM, 64M x 256N,
// 8 warps (2M x 4N), warp tile 32x64, KC=32 double-buffered cp.async.
// ---------------------------------------------------------------------------
#define KC        32
#define KSTRIDE   40                 // padded row stride (fp16 elems) — conflict-free
#define A_PLANE_E (64 * KSTRIDE)     // 2560
#define W_PLANE_E (256 * KSTRIDE)    // 10240
#define STAGE_E   (A_PLANE_E + W_PLANE_E)  // 12800 elems
#define STAGE_B   (STAGE_E * 2)      // 25600 bytes
#define SMEM_B    (2 * STAGE_B)      // 51200 bytes

#define OFF_A     0
#define OFF_W     A_PLANE_E

static __device__ __forceinline__ uint32_t smem_u32(const void* p) {
    uint32_t a;
    asm("{ .reg .u64 t; cvta.to.shared.u64 t, %1; cvt.u32.u64 %0, t; }" : "=r"(a) : "l"(p));
    return a;
}
static __device__ __forceinline__ void cp16(uint32_t saddr, const void* g) {
    asm volatile("cp.async.cg.shared.global [%0], [%1], 16;"
                 :: "r"(saddr), "l"((size_t)__cvta_generic_to_global(g)));
}
#define CP_COMMIT() asm volatile("cp.async.commit_group;" ::: "memory")
#define CP_WAIT(n)  asm volatile("cp.async.wait_group %0;" :: "n"(n) : "memory")

static __device__ __forceinline__ void mma16816(float* c, const uint32_t* a, const uint32_t* b) {
    asm volatile(
        "mma.sync.aligned.m16n8k16.row.col.f32.f16.f16.f32 "
        "{%0,%1,%2,%3}, {%4,%5,%6,%7}, {%8,%9}, {%0,%1,%2,%3};"
        : "+f"(c[0]), "+f"(c[1]), "+f"(c[2]), "+f"(c[3])
        : "r"(a[0]), "r"(a[1]), "r"(a[2]), "r"(a[3]), "r"(b[0]), "r"(b[1]));
}

__global__ void __launch_bounds__(256, 2) gemm_kernel(float* __restrict__ out, int tile_off, int B) {
    extern __shared__ __half smem[];
    const uint32_t sbase = smem_u32(smem);

    const int tid  = threadIdx.x;
    const int wid  = tid >> 5;
    const int lane = tid & 31;
    const int b0   = (tile_off + blockIdx.x) * 64;

    const int wm = (wid & 1) * 32;    // warp M offset (2 M-slots over 64)
    const int wn = (wid >> 1) * 64;   // warp N offset (4 N-slots over 256)
    const int qr = lane >> 2;         // 0..7
    const int qc = lane & 3;          // 0..3

    const int rowA = tid >> 2, segA = tid & 3;

    float acc[2][8][4];
#pragma unroll
    for (int mi = 0; mi < 2; mi++)
#pragma unroll
        for (int ni = 0; ni < 8; ni++)
#pragma unroll
            for (int j = 0; j < 4; j++)
                acc[mi][ni][j] = 0.f;

    auto prefetch = [&](int buf, int kc) {
        const uint32_t sb = sbase + (uint32_t)buf * STAGE_B;
        {
            const size_t go = (size_t)(b0 + rowA) * 512 + kc + segA * 8;
            const uint32_t so = (uint32_t)(rowA * KSTRIDE + segA * 8) * 2;
            cp16(sb + OFF_A * 2 + so, g_X + go);
        }
#pragma unroll
        for (int j = 0; j < 4; j++) {
            const int w   = tid + j * 256;
            const int row = w >> 2, seg = w & 3;
            const size_t go = (size_t)row * 512 + kc + seg * 8;
            const uint32_t so = (uint32_t)(row * KSTRIDE + seg * 8) * 2;
            cp16(sb + OFF_W * 2 + so, g_Wt + go);
        }
    };

    prefetch(0, 0);
    CP_COMMIT();

    for (int chunk = 0; chunk < 16; chunk++) {
        if (chunk + 1 < 16) {
            prefetch((chunk + 1) & 1, (chunk + 1) * KC);
            CP_COMMIT();
            CP_WAIT(1);          // current buffer's loads complete
        } else {
            CP_WAIT(0);
        }
        __syncthreads();

        const __half* st = smem + (chunk & 1) * STAGE_E;
        const __half* sA = st + OFF_A;
        const __half* sW = st + OFF_W;

#pragma unroll
        for (int kk = 0; kk < KC; kk += 16) {
            uint32_t a[2][4];
#pragma unroll
            for (int mi = 0; mi < 2; mi++) {
                const int r0 = wm + mi * 16 + qr;
                const int c0 = kk + qc * 2;
                a[mi][0] = *(const uint32_t*)(sA + (r0)     * KSTRIDE + c0);
                a[mi][1] = *(const uint32_t*)(sA + (r0 + 8) * KSTRIDE + c0);
                a[mi][2] = *(const uint32_t*)(sA + (r0)     * KSTRIDE + c0 + 8);
                a[mi][3] = *(const uint32_t*)(sA + (r0 + 8) * KSTRIDE + c0 + 8);
            }
#pragma unroll
            for (int ni = 0; ni < 8; ni++) {
                const int n  = wn + ni * 8 + qr;
                const int k0 = kk + qc * 2;
                uint32_t bw[2];
                bw[0] = *(const uint32_t*)(sW + n * KSTRIDE + k0);
                bw[1] = *(const uint32_t*)(sW + n * KSTRIDE + k0 + 8);
#pragma unroll
                for (int mi = 0; mi < 2; mi++)
                    mma16816(acc[mi][ni], a[mi], bw);
            }
        }
        __syncthreads();
    }

    // ---- epilogue: bias + swish + store ----
#pragma unroll
    for (int mi = 0; mi < 2; mi++) {
        const int row = b0 + wm + mi * 16 + qr;
#pragma unroll
        for (int ni = 0; ni < 8; ni++) {
            const int col = wn + ni * 8 + qc * 2;
            const float b_0 = g_bc[col], b_1 = g_bc[col + 1];

            if (row < B) {
                float z0 = acc[mi][ni][0] + b_0;
                float z1 = acc[mi][ni][1] + b_1;
                float2 o;
                o.x = z0 / (1.f + expf(-z0));
                o.y = z1 / (1.f + expf(-z1));
                *(float2*)(out + (size_t)row * E_DIM + col) = o;
            }
            if (row + 8 < B) {
                float z2 = acc[mi][ni][2] + b_0;
                float z3 = acc[mi][ni][3] + b_1;
                float2 o;
                o.x = z2 / (1.f + expf(-z2));
                o.y = z3 / (1.f + expf(-z3));
                *(float2*)(out + (size_t)(row + 8) * E_DIM + col) = o;
            }
        }
    }
}

// ---------------------------------------------------------------------------
// Launch: chunked gather->gemm pipeline across two streams (fork/join inside
// graph capture). Gather chunks run back-to-back on the capture stream; each
// gemm chunk runs on s1 after its gather chunk's event, overlapping the NEXT
// gather chunk (disjoint g_X regions). Streams/events created once on the
// uncaptured correctness call.
// ---------------------------------------------------------------------------
#define NCHUNK 4

extern "C" void kernel_launch(void* const* d_in, const int* in_sizes, int n_in,
                              void* d_out, int out_size) {
    const int*   nodes     = (const int*)  d_in[0];
    const int*   neigh_idx = (const int*)  d_in[1];
    const float* neigh_w   = (const float*)d_in[2];
    const float* features  = (const float*)d_in[3];
    const float* W_init    = (const float*)d_in[4];
    const float* b_init    = (const float*)d_in[5];
    const float* W_final   = (const float*)d_in[6];
    const float* b_final   = (const float*)d_in[7];
    float*       out       = (float*)d_out;

    const int B = in_sizes[0];

    static cudaStream_t s1 = nullptr;
    static cudaEvent_t  evG[NCHUNK];
    static cudaEvent_t  evJoin = nullptr;
    if (s1 == nullptr) {
        cudaStreamCreateWithFlags(&s1, cudaStreamNonBlocking);
        for (int i = 0; i < NCHUNK; i++)
            cudaEventCreateWithFlags(&evG[i], cudaEventDisableTiming);
        cudaEventCreateWithFlags(&evJoin, cudaEventDisableTiming);
        cudaFuncSetAttribute(gemm_kernel, cudaFuncAttributeMaxDynamicSharedMemorySize, SMEM_B);
    }

    setup_kernel<<<CONV_BLOCKS + 513, 256>>>(features, W_init, b_init, W_final, b_final);

    const int total_tiles = B_PAD / 64;            // 782
    const int base_tiles  = total_tiles / NCHUNK;  // 195
    int tile_off = 0;
    for (int c = 0; c < NCHUNK; c++) {
        const int tiles = (c < NCHUNK - 1) ? base_tiles : (total_tiles - base_tiles * (NCHUNK - 1));
        gather_kernel<<<tiles * 8, 256>>>(nodes, neigh_idx, neigh_w, features, tile_off * 64, B);
        cudaEventRecord(evG[c], 0);
        cudaStreamWaitEvent(s1, evG[c], 0);
        gemm_kernel<<<tiles, 256, SMEM_B, s1>>>(out, tile_off, B);
        tile_off += tiles;
    }
    // Join the fork back into the capture stream.
    cudaEventRecord(evJoin, s1);
    cudaStreamWaitEvent(0, evJoin, 0);
}

// round 16
// speedup vs baseline: 1.2327x; 1.2327x over previous
#include <cuda_runtime.h>
#include <cuda_fp16.h>
#include <cstdint>
#include <math.h>

// ---------------------------------------------------------------------------
// Shapes fixed by the dataset
#define D_DIM   256
#define E_DIM   256
#define K_NEIGH 32
#define N_NODES 200000
#define B_PAD   50048          // 782 * 64  (GEMM M-tile padded)

// Scratch (__device__ globals: no allocations allowed)
__device__ __half g_X [(size_t)B_PAD * 512];    // activation (fp16, single plane)
__device__ __half g_Wt[256 * 512];              // W^T single plane (fp16) [e][k]
__device__ float  g_bc[256];                    // fused bias
__device__ __half g_F16[(size_t)N_NODES * 256]; // fp16 feature table (self + neigh)

// ---------------------------------------------------------------------------
// Setup kernel: merged fp32->fp16 feature convert + fused-weight prep.
// Convert: 4 float4 per thread at COALESCED grid stride (MLP=4).
// blocks [0,12500): convert; [12500,13013): prep.
// ---------------------------------------------------------------------------
#define CONV_BLOCKS 12500
#define CONV_STRIDE ((size_t)CONV_BLOCKS * 256)     // 3.2M float4s per pass

__global__ void __launch_bounds__(256) setup_kernel(const float* __restrict__ features,
                                                    const float* __restrict__ W_init,
                                                    const float* __restrict__ b_init,
                                                    const float* __restrict__ W_final,
                                                    const float* __restrict__ b_final) {
    if (blockIdx.x < CONV_BLOCKS) {
        const size_t i0 = (size_t)blockIdx.x * 256 + threadIdx.x;
        float4 v0 = ((const float4*)features)[i0];
        float4 v1 = ((const float4*)features)[i0 + CONV_STRIDE];
        float4 v2 = ((const float4*)features)[i0 + 2 * CONV_STRIDE];
        float4 v3 = ((const float4*)features)[i0 + 3 * CONV_STRIDE];
        {
            __half2 p0 = __floats2half2_rn(v0.x, v0.y);
            __half2 p1 = __floats2half2_rn(v0.z, v0.w);
            uint2 u; u.x = *(uint32_t*)&p0; u.y = *(uint32_t*)&p1;
            *(uint2*)(g_F16 + i0 * 4) = u;
        }
        {
            __half2 p0 = __floats2half2_rn(v1.x, v1.y);
            __half2 p1 = __floats2half2_rn(v1.z, v1.w);
            uint2 u; u.x = *(uint32_t*)&p0; u.y = *(uint32_t*)&p1;
            *(uint2*)(g_F16 + (i0 + CONV_STRIDE) * 4) = u;
        }
        {
            __half2 p0 = __floats2half2_rn(v2.x, v2.y);
            __half2 p1 = __floats2half2_rn(v2.z, v2.w);
            uint2 u; u.x = *(uint32_t*)&p0; u.y = *(uint32_t*)&p1;
            *(uint2*)(g_F16 + (i0 + 2 * CONV_STRIDE) * 4) = u;
        }
        {
            __half2 p0 = __floats2half2_rn(v3.x, v3.y);
            __half2 p1 = __floats2half2_rn(v3.z, v3.w);
            uint2 u; u.x = *(uint32_t*)&p0; u.y = *(uint32_t*)&p1;
            *(uint2*)(g_F16 + (i0 + 3 * CONV_STRIDE) * 4) = u;
        }
        return;
    }

    __shared__ float sh[256];
    const int d = blockIdx.x - CONV_BLOCKS;
    const int e = threadIdx.x;

    if (d < 256) {
        sh[e] = W_init[d * 256 + e];
        __syncthreads();
        float s0 = 0.f, s1 = 0.f, s2 = 0.f, s3 = 0.f;
#pragma unroll 8
        for (int j = 0; j < 256; j += 4) {
            s0 += sh[j + 0] * W_final[(j + 0) * 256 + e];
            s1 += sh[j + 1] * W_final[(j + 1) * 256 + e];
            s2 += sh[j + 2] * W_final[(j + 2) * 256 + e];
            s3 += sh[j + 3] * W_final[(j + 3) * 256 + e];
        }
        g_Wt[e * 512 + d] = __float2half_rn((s0 + s1) + (s2 + s3));
    } else if (d < 512) {
        g_Wt[e * 512 + d] = __float2half_rn(W_final[d * 256 + e]);
    } else {
        sh[e] = b_init[e];
        __syncthreads();
        float s0 = 0.f, s1 = 0.f, s2 = 0.f, s3 = 0.f;
#pragma unroll 8
        for (int j = 0; j < 256; j += 4) {
            s0 += sh[j + 0] * W_final[(j + 0) * 256 + e];
            s1 += sh[j + 1] * W_final[(j + 1) * 256 + e];
            s2 += sh[j + 2] * W_final[(j + 2) * 256 + e];
            s3 += sh[j + 3] * W_final[(j + 3) * 256 + e];
        }
        g_bc[e] = b_final[e] + (s0 + s1) + (s2 + s3);
    }
}

// ---------------------------------------------------------------------------
// Kernel 1: gather + weighted-mean -> X fp16. BOTH paths read the fp16 table
// (fp32 features never touched -> L2 holds only the table). Self path is a
// raw 16B copy per lane, no conversion.
// ---------------------------------------------------------------------------
__global__ void __launch_bounds__(256) gather_kernel(const int*   __restrict__ nodes,
                                                     const int*   __restrict__ neigh_idx,
                                                     const float* __restrict__ neigh_w,
                                                     int B) {
    const int wid  = threadIdx.x >> 5;
    const int lane = threadIdx.x & 31;
    const int b    = blockIdx.x * 8 + wid;
    if (b >= B_PAD) return;

    __half* x = g_X + (size_t)b * 512;

    if (b < B) {
        // self: straight fp16 row copy (cols [0,256), lane covers lane*8..+8)
        const int node = nodes[b];
        uint4 sv = *(const uint4*)(g_F16 + (size_t)node * 256 + lane * 8);
        *(uint4*)(x + lane * 8) = sv;

        const float w_mine   = neigh_w[b * K_NEIGH + lane];
        const int   idx_mine = neigh_idx[b * K_NEIGH + lane];
        float ws = w_mine;
#pragma unroll
        for (int o = 16; o > 0; o >>= 1)
            ws += __shfl_xor_sync(0xffffffffu, ws, o);
        const float inv = 1.0f / ws;

        float4 a0 = make_float4(0.f, 0.f, 0.f, 0.f);
        float4 a1 = make_float4(0.f, 0.f, 0.f, 0.f);
#pragma unroll 8
        for (int k = 0; k < K_NEIGH; k++) {
            const float wk = __shfl_sync(0xffffffffu, w_mine, k) * inv;
            const int   ik = __shfl_sync(0xffffffffu, idx_mine, k);
            uint4 v = *(const uint4*)(g_F16 + (size_t)ik * 256 + lane * 8);
            float2 f0 = __half22float2(*(__half2*)&v.x);
            float2 f1 = __half22float2(*(__half2*)&v.y);
            float2 f2 = __half22float2(*(__half2*)&v.z);
            float2 f3 = __half22float2(*(__half2*)&v.w);
            a0.x += wk * f0.x; a0.y += wk * f0.y; a0.z += wk * f1.x; a0.w += wk * f1.y;
            a1.x += wk * f2.x; a1.y += wk * f2.y; a1.z += wk * f3.x; a1.w += wk * f3.y;
        }

        __half2 H0 = __floats2half2_rn(a0.x, a0.y);
        __half2 H1 = __floats2half2_rn(a0.z, a0.w);
        __half2 H2 = __floats2half2_rn(a1.x, a1.y);
        __half2 H3 = __floats2half2_rn(a1.z, a1.w);
        uint4 av;
        av.x = *(uint32_t*)&H0; av.y = *(uint32_t*)&H1;
        av.z = *(uint32_t*)&H2; av.w = *(uint32_t*)&H3;
        *(uint4*)(x + 256 + lane * 8) = av;
    } else {
        const uint4 z = make_uint4(0, 0, 0, 0);
        *(uint4*)(x + lane * 8)       = z;
        *(uint4*)(x + 256 + lane * 8) = z;
    }
}

// ---------------------------------------------------------------------------
// Kernel 2 (R14 proven): tensor-core GEMM, CTA tile 64M x 256N, 256 threads,
// 8 warps (2M x 4N), warp tile 32x64. KC=32 double-buffered cp.async.
// ---------------------------------------------------------------------------
#define KC        32
#define KSTRIDE   40                 // padded row stride (fp16 elems) — conflict-free
#define A_PLANE_E (64 * KSTRIDE)     // 2560
#define W_PLANE_E (256 * KSTRIDE)    // 10240
#define STAGE_E   (A_PLANE_E + W_PLANE_E)  // 12800 elems
#define STAGE_B   (STAGE_E * 2)      // 25600 bytes
#define SMEM_B    (2 * STAGE_B)      // 51200 bytes

#define OFF_A     0
#define OFF_W     A_PLANE_E

static __device__ __forceinline__ uint32_t smem_u32(const void* p) {
    uint32_t a;
    asm("{ .reg .u64 t; cvta.to.shared.u64 t, %1; cvt.u32.u64 %0, t; }" : "=r"(a) : "l"(p));
    return a;
}
static __device__ __forceinline__ void cp16(uint32_t saddr, const void* g) {
    asm volatile("cp.async.cg.shared.global [%0], [%1], 16;"
                 :: "r"(saddr), "l"((size_t)__cvta_generic_to_global(g)));
}
#define CP_COMMIT() asm volatile("cp.async.commit_group;" ::: "memory")
#define CP_WAIT(n)  asm volatile("cp.async.wait_group %0;" :: "n"(n) : "memory")

static __device__ __forceinline__ void mma16816(float* c, const uint32_t* a, const uint32_t* b) {
    asm volatile(
        "mma.sync.aligned.m16n8k16.row.col.f32.f16.f16.f32 "
        "{%0,%1,%2,%3}, {%4,%5,%6,%7}, {%8,%9}, {%0,%1,%2,%3};"
        : "+f"(c[0]), "+f"(c[1]), "+f"(c[2]), "+f"(c[3])
        : "r"(a[0]), "r"(a[1]), "r"(a[2]), "r"(a[3]), "r"(b[0]), "r"(b[1]));
}

__global__ void __launch_bounds__(256, 2) gemm_kernel(float* __restrict__ out, int B) {
    extern __shared__ __half smem[];
    const uint32_t sbase = smem_u32(smem);

    const int tid  = threadIdx.x;
    const int wid  = tid >> 5;
    const int lane = tid & 31;
    const int b0   = blockIdx.x * 64;

    const int wm = (wid & 1) * 32;    // warp M offset (2 M-slots over 64)
    const int wn = (wid >> 1) * 64;   // warp N offset (4 N-slots over 256)
    const int qr = lane >> 2;         // 0..7
    const int qc = lane & 3;          // 0..3

    const int rowA = tid >> 2, segA = tid & 3;

    float acc[2][8][4];
#pragma unroll
    for (int mi = 0; mi < 2; mi++)
#pragma unroll
        for (int ni = 0; ni < 8; ni++)
#pragma unroll
            for (int j = 0; j < 4; j++)
                acc[mi][ni][j] = 0.f;

    auto prefetch = [&](int buf, int kc) {
        const uint32_t sb = sbase + (uint32_t)buf * STAGE_B;
        {
            const size_t go = (size_t)(b0 + rowA) * 512 + kc + segA * 8;
            const uint32_t so = (uint32_t)(rowA * KSTRIDE + segA * 8) * 2;
            cp16(sb + OFF_A * 2 + so, g_X + go);
        }
#pragma unroll
        for (int j = 0; j < 4; j++) {
            const int w   = tid + j * 256;
            const int row = w >> 2, seg = w & 3;
            const size_t go = (size_t)row * 512 + kc + seg * 8;
            const uint32_t so = (uint32_t)(row * KSTRIDE + seg * 8) * 2;
            cp16(sb + OFF_W * 2 + so, g_Wt + go);
        }
    };

    prefetch(0, 0);
    CP_COMMIT();

    for (int chunk = 0; chunk < 16; chunk++) {
        if (chunk + 1 < 16) {
            prefetch((chunk + 1) & 1, (chunk + 1) * KC);
            CP_COMMIT();
            CP_WAIT(1);          // current buffer's loads complete
        } else {
            CP_WAIT(0);
        }
        __syncthreads();

        const __half* st = smem + (chunk & 1) * STAGE_E;
        const __half* sA = st + OFF_A;
        const __half* sW = st + OFF_W;

#pragma unroll
        for (int kk = 0; kk < KC; kk += 16) {
            uint32_t a[2][4];
#pragma unroll
            for (int mi = 0; mi < 2; mi++) {
                const int r0 = wm + mi * 16 + qr;
                const int c0 = kk + qc * 2;
                a[mi][0] = *(const uint32_t*)(sA + (r0)     * KSTRIDE + c0);
                a[mi][1] = *(const uint32_t*)(sA + (r0 + 8) * KSTRIDE + c0);
                a[mi][2] = *(const uint32_t*)(sA + (r0)     * KSTRIDE + c0 + 8);
                a[mi][3] = *(const uint32_t*)(sA + (r0 + 8) * KSTRIDE + c0 + 8);
            }
#pragma unroll
            for (int ni = 0; ni < 8; ni++) {
                const int n  = wn + ni * 8 + qr;
                const int k0 = kk + qc * 2;
                uint32_t bw[2];
                bw[0] = *(const uint32_t*)(sW + n * KSTRIDE + k0);
                bw[1] = *(const uint32_t*)(sW + n * KSTRIDE + k0 + 8);
#pragma unroll
                for (int mi = 0; mi < 2; mi++)
                    mma16816(acc[mi][ni], a[mi], bw);
            }
        }
        __syncthreads();
    }

    // ---- epilogue: bias + swish + store ----
#pragma unroll
    for (int mi = 0; mi < 2; mi++) {
        const int row = b0 + wm + mi * 16 + qr;
#pragma unroll
        for (int ni = 0; ni < 8; ni++) {
            const int col = wn + ni * 8 + qc * 2;
            const float b_0 = g_bc[col], b_1 = g_bc[col + 1];

            if (row < B) {
                float z0 = acc[mi][ni][0] + b_0;
                float z1 = acc[mi][ni][1] + b_1;
                float2 o;
                o.x = z0 / (1.f + expf(-z0));
                o.y = z1 / (1.f + expf(-z1));
                *(float2*)(out + (size_t)row * E_DIM + col) = o;
            }
            if (row + 8 < B) {
                float z2 = acc[mi][ni][2] + b_0;
                float z3 = acc[mi][ni][3] + b_1;
                float2 o;
                o.x = z2 / (1.f + expf(-z2));
                o.y = z3 / (1.f + expf(-z3));
                *(float2*)(out + (size_t)(row + 8) * E_DIM + col) = o;
            }
        }
    }
}

// ---------------------------------------------------------------------------
// Launch: sequential (R14 structure — overlap measured as a regression).
// ---------------------------------------------------------------------------
extern "C" void kernel_launch(void* const* d_in, const int* in_sizes, int n_in,
                              void* d_out, int out_size) {
    const int*   nodes     = (const int*)  d_in[0];
    const int*   neigh_idx = (const int*)  d_in[1];
    const float* neigh_w   = (const float*)d_in[2];
    const float* features  = (const float*)d_in[3];
    const float* W_init    = (const float*)d_in[4];
    const float* b_init    = (const float*)d_in[5];
    const float* W_final   = (const float*)d_in[6];
    const float* b_final   = (const float*)d_in[7];
    float*       out       = (float*)d_out;

    const int B = in_sizes[0];

    static bool attr_set = false;
    if (!attr_set) {
        cudaFuncSetAttribute(gemm_kernel, cudaFuncAttributeMaxDynamicSharedMemorySize, SMEM_B);
        attr_set = true;
    }

    setup_kernel<<<CONV_BLOCKS + 513, 256>>>(features, W_init, b_init, W_final, b_final);
    gather_kernel<<<B_PAD / 8, 256>>>(nodes, neigh_idx, neigh_w, B);
    gemm_kernel<<<B_PAD / 64, 256, SMEM_B>>>(out, B);
}

// round 17
// speedup vs baseline: 1.2988x; 1.0536x over previous
#include <cuda_runtime.h>
#include <cuda_fp16.h>
#include <cstdint>
#include <math.h>

// ---------------------------------------------------------------------------
// Shapes fixed by the dataset
#define D_DIM   256
#define E_DIM   256
#define K_NEIGH 32
#define N_NODES 200000
#define B_PAD   50048          // 782 * 64  (GEMM M-tile padded)

// Scratch (__device__ globals: no allocations allowed)
__device__ __half g_X [(size_t)B_PAD * 512];    // activation (fp16, single plane)
__device__ __half g_Wt[256 * 512];              // W^T single plane (fp16) [e][k]
__device__ float  g_bc[256];                    // fused bias
__device__ __half g_F16[(size_t)N_NODES * 256]; // fp16 feature table (self + neigh)

// ---------------------------------------------------------------------------
// Setup kernel: merged fp32->fp16 feature convert + fused-weight prep.
// Convert: 8 float4 per thread at COALESCED grid stride (MLP=8).
// blocks [0,6250): convert; [6250,6763): prep.
// ---------------------------------------------------------------------------
#define CONV_BLOCKS 6250
#define CONV_STRIDE ((size_t)CONV_BLOCKS * 256)     // 1.6M float4s per pass

__global__ void __launch_bounds__(256) setup_kernel(const float* __restrict__ features,
                                                    const float* __restrict__ W_init,
                                                    const float* __restrict__ b_init,
                                                    const float* __restrict__ W_final,
                                                    const float* __restrict__ b_final) {
    if (blockIdx.x < CONV_BLOCKS) {
        const size_t i0 = (size_t)blockIdx.x * 256 + threadIdx.x;
        float4 v[8];
#pragma unroll
        for (int j = 0; j < 8; j++)
            v[j] = ((const float4*)features)[i0 + (size_t)j * CONV_STRIDE];
#pragma unroll
        for (int j = 0; j < 8; j++) {
            __half2 p0 = __floats2half2_rn(v[j].x, v[j].y);
            __half2 p1 = __floats2half2_rn(v[j].z, v[j].w);
            uint2 u; u.x = *(uint32_t*)&p0; u.y = *(uint32_t*)&p1;
            *(uint2*)(g_F16 + (i0 + (size_t)j * CONV_STRIDE) * 4) = u;
        }
        return;
    }

    __shared__ float sh[256];
    const int d = blockIdx.x - CONV_BLOCKS;
    const int e = threadIdx.x;

    if (d < 256) {
        sh[e] = W_init[d * 256 + e];
        __syncthreads();
        float s0 = 0.f, s1 = 0.f, s2 = 0.f, s3 = 0.f;
#pragma unroll 8
        for (int j = 0; j < 256; j += 4) {
            s0 += sh[j + 0] * W_final[(j + 0) * 256 + e];
            s1 += sh[j + 1] * W_final[(j + 1) * 256 + e];
            s2 += sh[j + 2] * W_final[(j + 2) * 256 + e];
            s3 += sh[j + 3] * W_final[(j + 3) * 256 + e];
        }
        g_Wt[e * 512 + d] = __float2half_rn((s0 + s1) + (s2 + s3));
    } else if (d < 512) {
        g_Wt[e * 512 + d] = __float2half_rn(W_final[d * 256 + e]);
    } else {
        sh[e] = b_init[e];
        __syncthreads();
        float s0 = 0.f, s1 = 0.f, s2 = 0.f, s3 = 0.f;
#pragma unroll 8
        for (int j = 0; j < 256; j += 4) {
            s0 += sh[j + 0] * W_final[(j + 0) * 256 + e];
            s1 += sh[j + 1] * W_final[(j + 1) * 256 + e];
            s2 += sh[j + 2] * W_final[(j + 2) * 256 + e];
            s3 += sh[j + 3] * W_final[(j + 3) * 256 + e];
        }
        g_bc[e] = b_final[e] + (s0 + s1) + (s2 + s3);
    }
}

// ---------------------------------------------------------------------------
// Kernel 1 (R16 proven): gather + weighted-mean -> X fp16. Both paths read
// the fp16 table; self path is a raw 16B copy per lane.
// ---------------------------------------------------------------------------
__global__ void __launch_bounds__(256) gather_kernel(const int*   __restrict__ nodes,
                                                     const int*   __restrict__ neigh_idx,
                                                     const float* __restrict__ neigh_w,
                                                     int B) {
    const int wid  = threadIdx.x >> 5;
    const int lane = threadIdx.x & 31;
    const int b    = blockIdx.x * 8 + wid;
    if (b >= B_PAD) return;

    __half* x = g_X + (size_t)b * 512;

    if (b < B) {
        const int node = nodes[b];
        uint4 sv = *(const uint4*)(g_F16 + (size_t)node * 256 + lane * 8);
        *(uint4*)(x + lane * 8) = sv;

        const float w_mine   = neigh_w[b * K_NEIGH + lane];
        const int   idx_mine = neigh_idx[b * K_NEIGH + lane];
        float ws = w_mine;
#pragma unroll
        for (int o = 16; o > 0; o >>= 1)
            ws += __shfl_xor_sync(0xffffffffu, ws, o);
        const float inv = 1.0f / ws;

        float4 a0 = make_float4(0.f, 0.f, 0.f, 0.f);
        float4 a1 = make_float4(0.f, 0.f, 0.f, 0.f);
#pragma unroll 8
        for (int k = 0; k < K_NEIGH; k++) {
            const float wk = __shfl_sync(0xffffffffu, w_mine, k) * inv;
            const int   ik = __shfl_sync(0xffffffffu, idx_mine, k);
            uint4 v = *(const uint4*)(g_F16 + (size_t)ik * 256 + lane * 8);
            float2 f0 = __half22float2(*(__half2*)&v.x);
            float2 f1 = __half22float2(*(__half2*)&v.y);
            float2 f2 = __half22float2(*(__half2*)&v.z);
            float2 f3 = __half22float2(*(__half2*)&v.w);
            a0.x += wk * f0.x; a0.y += wk * f0.y; a0.z += wk * f1.x; a0.w += wk * f1.y;
            a1.x += wk * f2.x; a1.y += wk * f2.y; a1.z += wk * f3.x; a1.w += wk * f3.y;
        }

        __half2 H0 = __floats2half2_rn(a0.x, a0.y);
        __half2 H1 = __floats2half2_rn(a0.z, a0.w);
        __half2 H2 = __floats2half2_rn(a1.x, a1.y);
        __half2 H3 = __floats2half2_rn(a1.z, a1.w);
        uint4 av;
        av.x = *(uint32_t*)&H0; av.y = *(uint32_t*)&H1;
        av.z = *(uint32_t*)&H2; av.w = *(uint32_t*)&H3;
        *(uint4*)(x + 256 + lane * 8) = av;
    } else {
        const uint4 z = make_uint4(0, 0, 0, 0);
        *(uint4*)(x + lane * 8)       = z;
        *(uint4*)(x + 256 + lane * 8) = z;
    }
}

// ---------------------------------------------------------------------------
// Kernel 2: tensor-core GEMM, CTA tile 64M x 256N, 8 warps (2M x 4N),
// warp tile 32x64. KC=32, THREE-stage cp.async pipeline, ldmatrix fragment
// loads (6 LDSM per 16-K step instead of 24 LDS.32). 2 CTAs/SM.
// ---------------------------------------------------------------------------
#define KC        32
#define KSTRIDE   40                 // padded row stride (fp16 elems) — conflict-free
#define A_PLANE_E (64 * KSTRIDE)     // 2560
#define W_PLANE_E (256 * KSTRIDE)    // 10240
#define STAGE_E   (A_PLANE_E + W_PLANE_E)  // 12800 elems
#define STAGE_B   (STAGE_E * 2)      // 25600 bytes
#define NSTAGE    3
#define SMEM_B    (NSTAGE * STAGE_B) // 76800 bytes

#define OFF_A     0
#define OFF_W     A_PLANE_E

static __device__ __forceinline__ uint32_t smem_u32(const void* p) {
    uint32_t a;
    asm("{ .reg .u64 t; cvta.to.shared.u64 t, %1; cvt.u32.u64 %0, t; }" : "=r"(a) : "l"(p));
    return a;
}
static __device__ __forceinline__ void cp16(uint32_t saddr, const void* g) {
    asm volatile("cp.async.cg.shared.global [%0], [%1], 16;"
                 :: "r"(saddr), "l"((size_t)__cvta_generic_to_global(g)));
}
#define CP_COMMIT() asm volatile("cp.async.commit_group;" ::: "memory")
#define CP_WAIT(n)  asm volatile("cp.async.wait_group %0;" :: "n"(n) : "memory")

#define LDSM_X4(r0, r1, r2, r3, addr) \
    asm volatile("ldmatrix.sync.aligned.m8n8.x4.shared.b16 {%0,%1,%2,%3}, [%4];" \
        : "=r"(r0), "=r"(r1), "=r"(r2), "=r"(r3) : "r"(addr))

static __device__ __forceinline__ void mma16816(float* c, const uint32_t* a, const uint32_t* b) {
    asm volatile(
        "mma.sync.aligned.m16n8k16.row.col.f32.f16.f16.f32 "
        "{%0,%1,%2,%3}, {%4,%5,%6,%7}, {%8,%9}, {%0,%1,%2,%3};"
        : "+f"(c[0]), "+f"(c[1]), "+f"(c[2]), "+f"(c[3])
        : "r"(a[0]), "r"(a[1]), "r"(a[2]), "r"(a[3]), "r"(b[0]), "r"(b[1]));
}

__global__ void __launch_bounds__(256, 2) gemm_kernel(float* __restrict__ out, int B) {
    extern __shared__ __half smem[];
    const uint32_t sbase = smem_u32(smem);

    const int tid  = threadIdx.x;
    const int wid  = tid >> 5;
    const int lane = tid & 31;
    const int b0   = blockIdx.x * 64;

    const int wm = (wid & 1) * 32;    // warp M offset (2 M-slots over 64)
    const int wn = (wid >> 1) * 64;   // warp N offset (4 N-slots over 256)
    const int qr = lane >> 2;         // 0..7
    const int qc = lane & 3;          // 0..3

    const int rowA = tid >> 2, segA = tid & 3;

    // ---- ldmatrix per-lane byte offsets (relative to stage base) ----
    // A: x4 tiles t0=(r+0,k+0) t1=(r+8,k+0) t2=(r+0,k+8) t3=(r+8,k+8)
    //    -> regs a0..a3 exactly match mma A-fragment order.
    // W: x4 covers an ni-pair: t0=(ni,k+0) t1=(ni,k+8) t2=(ni+1,k+0) t3=(ni+1,k+8)
    uint32_t offA[2], offW[4];
    {
        const int t  = lane >> 3;     // 0..3
        const int rr = lane & 7;
#pragma unroll
        for (int mi = 0; mi < 2; mi++) {
            const int row = wm + mi * 16 + rr + (t & 1) * 8;
            const int col = (t >> 1) * 8;
            offA[mi] = (uint32_t)(OFF_A + row * KSTRIDE + col) * 2;
        }
#pragma unroll
        for (int p = 0; p < 4; p++) {
            const int ni = 2 * p + (t >> 1);
            const int n  = wn + ni * 8 + rr;
            const int ka = (t & 1) * 8;
            offW[p] = (uint32_t)(OFF_W + n * KSTRIDE + ka) * 2;
        }
    }

    float acc[2][8][4];
#pragma unroll
    for (int mi = 0; mi < 2; mi++)
#pragma unroll
        for (int ni = 0; ni < 8; ni++)
#pragma unroll
            for (int j = 0; j < 4; j++)
                acc[mi][ni][j] = 0.f;

    auto prefetch = [&](int buf, int kc) {
        const uint32_t sb = sbase + (uint32_t)buf * STAGE_B;
        {
            const size_t go = (size_t)(b0 + rowA) * 512 + kc + segA * 8;
            const uint32_t so = (uint32_t)(rowA * KSTRIDE + segA * 8) * 2;
            cp16(sb + OFF_A * 2 + so, g_X + go);
        }
#pragma unroll
        for (int j = 0; j < 4; j++) {
            const int w   = tid + j * 256;
            const int row = w >> 2, seg = w & 3;
            const size_t go = (size_t)row * 512 + kc + seg * 8;
            const uint32_t so = (uint32_t)(row * KSTRIDE + seg * 8) * 2;
            cp16(sb + OFF_W * 2 + so, g_Wt + go);
        }
    };

    prefetch(0, 0);
    CP_COMMIT();
    prefetch(1, KC);
    CP_COMMIT();

    for (int chunk = 0; chunk < 16; chunk++) {
        if (chunk + 2 < 16) {
            prefetch((chunk + 2) % NSTAGE, (chunk + 2) * KC);
            CP_COMMIT();
            CP_WAIT(2);          // chunk's buffer complete (≤2 groups pending)
        } else if (chunk + 1 < 16) {
            CP_WAIT(1);
        } else {
            CP_WAIT(0);
        }
        __syncthreads();

        const uint32_t sb = sbase + (uint32_t)(chunk % NSTAGE) * STAGE_B;

#pragma unroll
        for (int kk = 0; kk < KC; kk += 16) {
            uint32_t a[2][4];
#pragma unroll
            for (int mi = 0; mi < 2; mi++)
                LDSM_X4(a[mi][0], a[mi][1], a[mi][2], a[mi][3], sb + offA[mi] + kk * 2);

            uint32_t bw[8][2];
#pragma unroll
            for (int p = 0; p < 4; p++) {
                uint32_t r0, r1, r2, r3;
                LDSM_X4(r0, r1, r2, r3, sb + offW[p] + kk * 2);
                bw[2 * p + 0][0] = r0; bw[2 * p + 0][1] = r1;
                bw[2 * p + 1][0] = r2; bw[2 * p + 1][1] = r3;
            }

#pragma unroll
            for (int ni = 0; ni < 8; ni++)
#pragma unroll
                for (int mi = 0; mi < 2; mi++)
                    mma16816(acc[mi][ni], a[mi], bw[ni]);
        }
        __syncthreads();   // buffer consumed; later prefetch may overwrite it
    }

    // ---- epilogue: bias + swish + store ----
#pragma unroll
    for (int mi = 0; mi < 2; mi++) {
        const int row = b0 + wm + mi * 16 + qr;
#pragma unroll
        for (int ni = 0; ni < 8; ni++) {
            const int col = wn + ni * 8 + qc * 2;
            const float b_0 = g_bc[col], b_1 = g_bc[col + 1];

            if (row < B) {
                float z0 = acc[mi][ni][0] + b_0;
                float z1 = acc[mi][ni][1] + b_1;
                float2 o;
                o.x = z0 / (1.f + expf(-z0));
                o.y = z1 / (1.f + expf(-z1));
                *(float2*)(out + (size_t)row * E_DIM + col) = o;
            }
            if (row + 8 < B) {
                float z2 = acc[mi][ni][2] + b_0;
                float z3 = acc[mi][ni][3] + b_1;
                float2 o;
                o.x = z2 / (1.f + expf(-z2));
                o.y = z3 / (1.f + expf(-z3));
                *(float2*)(out + (size_t)(row + 8) * E_DIM + col) = o;
            }
        }
    }
}

// ---------------------------------------------------------------------------
// Launch: sequential (overlap measured as a regression in R15).
// ---------------------------------------------------------------------------
extern "C" void kernel_launch(void* const* d_in, const int* in_sizes, int n_in,
                              void* d_out, int out_size) {
    const int*   nodes     = (const int*)  d_in[0];
    const int*   neigh_idx = (const int*)  d_in[1];
    const float* neigh_w   = (const float*)d_in[2];
    const float* features  = (const float*)d_in[3];
    const float* W_init    = (const float*)d_in[4];
    const float* b_init    = (const float*)d_in[5];
    const float* W_final   = (const float*)d_in[6];
    const float* b_final   = (const float*)d_in[7];
    float*       out       = (float*)d_out;

    const int B = in_sizes[0];

    static bool attr_set = false;
    if (!attr_set) {
        cudaFuncSetAttribute(gemm_kernel, cudaFuncAttributeMaxDynamicSharedMemorySize, SMEM_B);
        attr_set = true;
    }

    setup_kernel<<<CONV_BLOCKS + 513, 256>>>(features, W_init, b_init, W_final, b_final);
    gather_kernel<<<B_PAD / 8, 256>>>(nodes, neigh_idx, neigh_w, B);
    gemm_kernel<<<B_PAD / 64, 256, SMEM_B>>>(out, B);
}